// round 7
// baseline (speedup 1.0000x reference)
#include <cuda_runtime.h>
#include <cstdint>

// RiemannCurvatureTensor: out = [ricci(4096x4096 f32, zero except top-left
// 32x32 gather-reduce block), trace scalar].
// 64MB zero-fill via TMA bulk stores (cp.async.bulk SMEM->GMEM) to bypass the
// LSU/L1tex store-issue bottleneck; corner + scalar patched by block 0.

#define MAX_DIM 32
#define CHUNK   32768                     // 32KB per bulk store
#define BLK0_CHUNKS 16                    // block 0 covers 512KB (rows 0..31)
#define REG_CHUNKS  4                     // other blocks cover 128KB each

__device__ __forceinline__ uint32_t smem_u32(const void* p) {
    uint32_t a;
    asm("{ .reg .u64 t; cvta.to.shared.u64 t, %1; cvt.u32.u64 %0, t; }"
        : "=r"(a) : "l"(p));
    return a;
}

__global__ __launch_bounds__(256, 6)
void ricci_tma_kernel(const float* __restrict__ comp,
                      const int* __restrict__ gidx,
                      const float* __restrict__ gsgn,
                      float* __restrict__ out,
                      int out_size)
{
    __shared__ alignas(128) float4 zbuf[CHUNK / 16];   // 32KB of zeros

    const int tid = threadIdx.x;

    // --- zero the SMEM staging buffer (8 x STS.128 per thread) ---
    const float4 z = make_float4(0.f, 0.f, 0.f, 0.f);
    #pragma unroll
    for (int it = 0; it < (CHUNK / 16) / 256; ++it)
        zbuf[tid + it * 256] = z;
    // order generic STS before async-proxy TMA reads
    asm volatile("fence.proxy.async.shared::cta;" ::: "memory");
    __syncthreads();

    const uint32_t sbuf = smem_u32(zbuf);
    char* const out_b = (char*)out;

    // --- issue bulk zero stores ---
    const bool is0 = (blockIdx.x == 0);
    const long long base = is0 ? 0LL
        : (long long)BLK0_CHUNKS * CHUNK + (long long)(blockIdx.x - 1) * (REG_CHUNKS * CHUNK);
    const int nchunks = is0 ? BLK0_CHUNKS : REG_CHUNKS;

    if (tid == 0) {
        const unsigned csz = CHUNK;
        for (int c = 0; c < nchunks; ++c) {
            asm volatile(
                "cp.async.bulk.global.shared::cta.bulk_group [%0], [%1], %2;"
                :: "l"(out_b + base + (long long)c * CHUNK), "r"(sbuf), "r"(csz)
                : "memory");
        }
        asm volatile("cp.async.bulk.commit_group;" ::: "memory");
    }

    if (is0) {
        // --- corner gather-reduce, overlapped with the TMA drain ---
        // element e = tid + c*256 -> i = e>>5, j = e&31 (coalesced STG later)
        float vals[4];
        #pragma unroll
        for (int c = 0; c < 4; ++c) {
            const int e = tid + c * 256;
            const int i = e >> 5;
            const int j = e & 31;
            float acc = 0.f;
            #pragma unroll
            for (int k = 0; k < MAX_DIM; ++k) {
                const int t = k * (MAX_DIM * MAX_DIM) + i * MAX_DIM + j;
                acc = fmaf(gsgn[t], comp[gidx[t]], acc);
            }
            vals[c] = acc;
        }

        // trace of the corner block (rest of diagonal is zero)
        float tr = 0.f;
        if (tid < 32) {
            const int i = tid;
            #pragma unroll
            for (int k = 0; k < MAX_DIM; ++k) {
                const int t = k * (MAX_DIM * MAX_DIM) + i * MAX_DIM + i;
                tr = fmaf(gsgn[t], comp[gidx[t]], tr);
            }
            #pragma unroll
            for (int off = 16; off > 0; off >>= 1)
                tr += __shfl_xor_sync(0xffffffffu, tr, off);
        }

        // --- wait for our zero-fill of rows 0..31, then patch corner ---
        if (tid == 0)
            asm volatile("cp.async.bulk.wait_group 0;" ::: "memory");
        __syncthreads();

        #pragma unroll
        for (int c = 0; c < 4; ++c) {
            const int e = tid + c * 256;
            const int i = e >> 5;
            const int j = e & 31;
            out[i * 4096 + j] = vals[c];
        }
        if (tid == 0 && (out_size & 3) != 0)
            out[(long long)(out_size >> 2) << 2] = tr;   // trailing scalar
    } else {
        if (tid == 0)
            asm volatile("cp.async.bulk.wait_group 0;" ::: "memory");
    }
}

extern "C" void kernel_launch(void* const* d_in, const int* in_sizes, int n_in,
                              void* d_out, int out_size)
{
    const float* comp = (const float*)d_in[0];   // components [10000] f32
    const int*   gidx = (const int*)d_in[1];     // gather_idx [32,32,32] i32
    const float* gsgn = (const float*)d_in[2];   // gather_sign [32,32,32] f32
    float* out = (float*)d_out;

    // 64MB = block0 (16*32KB) + 508 blocks * (4*32KB)
    const int blocks = 1 + 508;
    ricci_tma_kernel<<<blocks, 256>>>(comp, gidx, gsgn, out, out_size);
}

// round 16
// speedup vs baseline: 1.1032x; 1.1032x over previous
#include <cuda_runtime.h>
#include <cstdint>

// RiemannCurvatureTensor: out = [ricci(4096x4096 f32, zero except top-left
// 32x32 block), trace scalar].
// Hybrid fill: rows 0..2303 (36MB) via per-thread STG.128 (measured 3.05 TB/s),
// rows 2304..4095 (28MB) via TMA bulk stores (measured 2.34 TB/s), issued
// concurrently from every block. Disjoint regions -> no ordering needed.

#define MAX_DIM   32
#define ROW_BYTES 16384                    // one 4096-f32 row = 16KB = 1 TMA chunk
#define STG_ROWS  2304                     // 36MB via STG
#define TMA_ROWS  1792                     // 28MB via TMA (rows 2304..4095)

__device__ __forceinline__ uint32_t smem_u32(const void* p) {
    uint32_t a;
    asm("{ .reg .u64 t; cvta.to.shared.u64 t, %1; cvt.u32.u64 %0, t; }"
        : "=r"(a) : "l"(p));
    return a;
}

__global__ __launch_bounds__(256, 8)
void ricci_hybrid_kernel(const float* __restrict__ comp,
                         const int* __restrict__ gidx,
                         const float* __restrict__ gsgn,
                         float* __restrict__ out,
                         int out_size)
{
    __shared__ alignas(128) float4 zbuf[ROW_BYTES / 16];   // 16KB of zeros

    const int tid = threadIdx.x;
    const float4 z = make_float4(0.f, 0.f, 0.f, 0.f);

    // zero the SMEM staging buffer (4 x STS.128 per thread)
    #pragma unroll
    for (int it = 0; it < (ROW_BYTES / 16) / 256; ++it)
        zbuf[tid + it * 256] = z;
    asm volatile("fence.proxy.async.shared::cta;" ::: "memory");
    __syncthreads();

    // ---- TMA side: rows 2304..4095, one 16KB row per chunk ----
    if (tid == 0) {
        const uint32_t sbuf = smem_u32(zbuf);
        char* const out_b = (char*)out;
        const unsigned csz = ROW_BYTES;
        for (int c = blockIdx.x; c < TMA_ROWS; c += gridDim.x) {
            asm volatile(
                "cp.async.bulk.global.shared::cta.bulk_group [%0], [%1], %2;"
                :: "l"(out_b + (long long)(STG_ROWS + c) * ROW_BYTES),
                   "r"(sbuf), "r"(csz)
                : "memory");
        }
        asm volatile("cp.async.bulk.commit_group;" ::: "memory");
    }

    // ---- STG side: rows 0..2303 grid-stride, corner computed inline ----
    {
        const int n4 = STG_ROWS * 1024;                  // float4 count (36MB)
        const int stride = gridDim.x * blockDim.x;
        float4* __restrict__ out4 = (float4*)out;
        const int CORNER_ROWS_V4 = MAX_DIM << 10;        // rows 0..31 in v-space
        const int CORNER_COLS_V4 = MAX_DIM / 4;          // first 8 float4s per row

        for (int v = blockIdx.x * blockDim.x + tid; v < n4; v += stride) {
            if (v < CORNER_ROWS_V4 && (v & 1023) < CORNER_COLS_V4) {
                const int i = v >> 10;
                const int col = (v & 1023) * 4;
                float vals[4];
                #pragma unroll
                for (int c = 0; c < 4; ++c) {
                    const int j = col + c;
                    float acc = 0.f;
                    #pragma unroll
                    for (int k = 0; k < MAX_DIM; ++k) {
                        const int t = k * (MAX_DIM * MAX_DIM) + i * MAX_DIM + j;
                        acc = fmaf(gsgn[t], comp[gidx[t]], acc);
                    }
                    vals[c] = acc;
                }
                out4[v] = make_float4(vals[0], vals[1], vals[2], vals[3]);
            } else {
                out4[v] = z;
            }
        }
    }

    // ---- trailing scalar (beyond the 64MB tensor; no TMA overlap) ----
    if ((out_size & 3) != 0 && blockIdx.x == 0 && tid < 32) {
        const int i = tid;
        float tr = 0.f;
        #pragma unroll
        for (int k = 0; k < MAX_DIM; ++k) {
            const int t = k * (MAX_DIM * MAX_DIM) + i * MAX_DIM + i;
            tr = fmaf(gsgn[t], comp[gidx[t]], tr);
        }
        #pragma unroll
        for (int off = 16; off > 0; off >>= 1)
            tr += __shfl_xor_sync(0xffffffffu, tr, off);
        if (tid == 0)
            out[(long long)(out_size >> 2) << 2] = tr;
    }

    // drain this block's TMA stores before block exit
    if (tid == 0)
        asm volatile("cp.async.bulk.wait_group 0;" ::: "memory");
}

extern "C" void kernel_launch(void* const* d_in, const int* in_sizes, int n_in,
                              void* d_out, int out_size)
{
    const float* comp = (const float*)d_in[0];   // components [10000] f32
    const int*   gidx = (const int*)d_in[1];     // gather_idx [32,32,32] i32
    const float* gsgn = (const float*)d_in[2];   // gather_sign [32,32,32] f32
    float* out = (float*)d_out;

    // One full wave on GB300 (152 SMs x 8 blocks), 16KB smem each.
    const int blocks = 152 * 8;                  // 1216
    ricci_hybrid_kernel<<<blocks, 256>>>(comp, gidx, gsgn, out, out_size);
}